// round 1
// baseline (speedup 1.0000x reference)
#include <cuda_runtime.h>
#include <math.h>

// Problem constants
#define Bq 8
#define Tt 1024
#define Ee 512
#define Hh 8
#define BT (Bq*Tt)     // 8192
#define HE (Hh*Ee)     // 4096

// ---------------- scratch (static device globals; no allocation) -------------
__device__ float g_Q[(size_t)BT*HE];            // 128 MiB
__device__ float g_K[(size_t)BT*HE];            // 128 MiB
__device__ float g_V[(size_t)BT*HE];            // 128 MiB
__device__ float g_S[(size_t)Bq*Hh*Tt*Tt];      // 256 MiB (scores -> probs in place)
__device__ float g_w[Bq*Hh*Tt];                 // column sums of attn
__device__ float g_o[Bq*HE];                    // sum_t attention output
__device__ float g_u[Bq*Ee];                    // relu(o @ Wu + bu)
__device__ float g_y1[(size_t)BT*Ee];           // after first LN
__device__ float g_r[(size_t)BT*Ee];            // relu(y1 @ Wh + bh)

// ---------------- generic NN GEMM:  C = A(MxK) @ B(KxN) + bias, opt ReLU -----
// lda = K, ldb = N, ldc = N.  M%128==0, N%128==0, K%16==0 assumed.
template<int RELU>
__global__ __launch_bounds__(256) void gemm_nn_bias(
    const float* __restrict__ A, const float* __restrict__ B,
    const float* __restrict__ bias, float* __restrict__ C,
    int M, int N, int K)
{
    const int BM=128, BN=128, BK=16;
    __shared__ float As[BK][BM+1];
    __shared__ float Bs[BK][BN];

    int tid  = threadIdx.x;
    int row0 = blockIdx.y * BM;
    int col0 = blockIdx.x * BN;

    const float* Ap = A + (size_t)row0 * K;
    const float* Bp = B + col0;

    int aR = tid >> 2;            // 0..63
    int aC = (tid & 3) << 2;      // 0,4,8,12
    int bR = tid >> 5;            // 0..7
    int bC = (tid & 31) << 2;     // 0..124

    int tr = (tid >> 4) << 3;     // 0..120
    int tc = (tid & 15) << 3;

    float acc[8][8];
    #pragma unroll
    for (int i=0;i<8;i++)
        #pragma unroll
        for (int j=0;j<8;j++) acc[i][j]=0.f;

    for (int k0 = 0; k0 < K; k0 += BK) {
        float4 a0 = *(const float4*)(Ap + (size_t)aR      * K + k0 + aC);
        float4 a1 = *(const float4*)(Ap + (size_t)(aR+64) * K + k0 + aC);
        As[aC+0][aR]    = a0.x; As[aC+1][aR]    = a0.y;
        As[aC+2][aR]    = a0.z; As[aC+3][aR]    = a0.w;
        As[aC+0][aR+64] = a1.x; As[aC+1][aR+64] = a1.y;
        As[aC+2][aR+64] = a1.z; As[aC+3][aR+64] = a1.w;

        float4 b0 = *(const float4*)(Bp + (size_t)(k0+bR)   * N + bC);
        float4 b1 = *(const float4*)(Bp + (size_t)(k0+bR+8) * N + bC);
        *(float4*)&Bs[bR][bC]   = b0;
        *(float4*)&Bs[bR+8][bC] = b1;
        __syncthreads();

        #pragma unroll
        for (int kk=0; kk<BK; kk++) {
            float ra[8], rb[8];
            #pragma unroll
            for (int i=0;i<8;i++) ra[i] = As[kk][tr+i];
            #pragma unroll
            for (int j=0;j<8;j++) rb[j] = Bs[kk][tc+j];
            #pragma unroll
            for (int i=0;i<8;i++)
                #pragma unroll
                for (int j=0;j<8;j++)
                    acc[i][j] = fmaf(ra[i], rb[j], acc[i][j]);
        }
        __syncthreads();
    }

    #pragma unroll
    for (int i=0;i<8;i++) {
        float* crow = C + (size_t)(row0+tr+i) * N + col0 + tc;
        #pragma unroll
        for (int j4=0;j4<8;j4+=4) {
            float4 bb = *(const float4*)(bias + col0 + tc + j4);
            float4 v;
            v.x = acc[i][j4+0] + bb.x;
            v.y = acc[i][j4+1] + bb.y;
            v.z = acc[i][j4+2] + bb.z;
            v.w = acc[i][j4+3] + bb.w;
            if (RELU) {
                v.x = fmaxf(v.x,0.f); v.y = fmaxf(v.y,0.f);
                v.z = fmaxf(v.z,0.f); v.w = fmaxf(v.w,0.f);
            }
            *(float4*)(crow + j4) = v;
        }
    }
}

// ---------------- batched NT GEMM for scores: S = (Q_h @ K_h^T) / E ----------
// blockIdx.z = b*8+h; per head: M=N=1024, K=512, lda=ldb=HE, ldc=Tt
__global__ __launch_bounds__(256) void gemm_nt_scores()
{
    const int BM=128, BN=128, BK=16;
    int z = blockIdx.z;
    int b = z >> 3, h = z & 7;
    const float* Ap = g_Q + (size_t)b*Tt*HE + (size_t)h*Ee + (size_t)blockIdx.y*BM*HE;
    const float* Bp = g_K + (size_t)b*Tt*HE + (size_t)h*Ee + (size_t)blockIdx.x*BN*HE;
    float*       Cp = g_S + (size_t)z*Tt*Tt;

    __shared__ float As[BK][BM+1];
    __shared__ float Bs[BK][BN+1];

    int tid = threadIdx.x;
    int aR = tid >> 2;
    int aC = (tid & 3) << 2;
    int tr = (tid >> 4) << 3;
    int tc = (tid & 15) << 3;

    float acc[8][8];
    #pragma unroll
    for (int i=0;i<8;i++)
        #pragma unroll
        for (int j=0;j<8;j++) acc[i][j]=0.f;

    for (int k0 = 0; k0 < Ee; k0 += BK) {
        float4 a0 = *(const float4*)(Ap + (size_t)aR      * HE + k0 + aC);
        float4 a1 = *(const float4*)(Ap + (size_t)(aR+64) * HE + k0 + aC);
        As[aC+0][aR]    = a0.x; As[aC+1][aR]    = a0.y;
        As[aC+2][aR]    = a0.z; As[aC+3][aR]    = a0.w;
        As[aC+0][aR+64] = a1.x; As[aC+1][aR+64] = a1.y;
        As[aC+2][aR+64] = a1.z; As[aC+3][aR+64] = a1.w;

        float4 b0 = *(const float4*)(Bp + (size_t)aR      * HE + k0 + aC);
        float4 b1 = *(const float4*)(Bp + (size_t)(aR+64) * HE + k0 + aC);
        Bs[aC+0][aR]    = b0.x; Bs[aC+1][aR]    = b0.y;
        Bs[aC+2][aR]    = b0.z; Bs[aC+3][aR]    = b0.w;
        Bs[aC+0][aR+64] = b1.x; Bs[aC+1][aR+64] = b1.y;
        Bs[aC+2][aR+64] = b1.z; Bs[aC+3][aR+64] = b1.w;
        __syncthreads();

        #pragma unroll
        for (int kk=0; kk<BK; kk++) {
            float ra[8], rb[8];
            #pragma unroll
            for (int i=0;i<8;i++) ra[i] = As[kk][tr+i];
            #pragma unroll
            for (int j=0;j<8;j++) rb[j] = Bs[kk][tc+j];
            #pragma unroll
            for (int i=0;i<8;i++)
                #pragma unroll
                for (int j=0;j<8;j++)
                    acc[i][j] = fmaf(ra[i], rb[j], acc[i][j]);
        }
        __syncthreads();
    }

    const float scale = 1.f / (float)Ee;   // both q and k scaled by 1/sqrt(E)
    int row0 = blockIdx.y*BM, col0 = blockIdx.x*BN;
    #pragma unroll
    for (int i=0;i<8;i++) {
        float* crow = Cp + (size_t)(row0+tr+i) * Tt + col0 + tc;
        #pragma unroll
        for (int j4=0;j4<8;j4+=4) {
            float4 v;
            v.x = acc[i][j4+0]*scale; v.y = acc[i][j4+1]*scale;
            v.z = acc[i][j4+2]*scale; v.w = acc[i][j4+3]*scale;
            *(float4*)(crow + j4) = v;
        }
    }
}

// ---------------- softmax over each score row (in place), 128 thr/row --------
__global__ __launch_bounds__(128) void softmax_inplace()
{
    float* row = g_S + (size_t)blockIdx.x * Tt;
    int tid = threadIdx.x;
    float4 v0 = ((float4*)row)[tid];
    float4 v1 = ((float4*)row)[tid + 128];

    float m = fmaxf(fmaxf(fmaxf(v0.x,v0.y),fmaxf(v0.z,v0.w)),
                    fmaxf(fmaxf(v1.x,v1.y),fmaxf(v1.z,v1.w)));
    #pragma unroll
    for (int o=16;o>0;o>>=1) m = fmaxf(m, __shfl_xor_sync(0xffffffffu, m, o));
    __shared__ float sm[4], ss[4];
    if ((tid&31)==0) sm[tid>>5] = m;
    __syncthreads();
    m = fmaxf(fmaxf(sm[0],sm[1]), fmaxf(sm[2],sm[3]));

    v0.x = expf(v0.x-m); v0.y = expf(v0.y-m); v0.z = expf(v0.z-m); v0.w = expf(v0.w-m);
    v1.x = expf(v1.x-m); v1.y = expf(v1.y-m); v1.z = expf(v1.z-m); v1.w = expf(v1.w-m);
    float s = v0.x+v0.y+v0.z+v0.w + v1.x+v1.y+v1.z+v1.w;
    #pragma unroll
    for (int o=16;o>0;o>>=1) s += __shfl_xor_sync(0xffffffffu, s, o);
    if ((tid&31)==0) ss[tid>>5] = s;
    __syncthreads();
    s = ss[0]+ss[1]+ss[2]+ss[3];
    float inv = 1.f / s;
    v0.x*=inv; v0.y*=inv; v0.z*=inv; v0.w*=inv;
    v1.x*=inv; v1.y*=inv; v1.z*=inv; v1.w*=inv;
    ((float4*)row)[tid]       = v0;
    ((float4*)row)[tid + 128] = v1;
}

// ---------------- w[bh,k] = sum_q attn[bh,q,k] -------------------------------
__global__ __launch_bounds__(256) void attn_colsum()
{
    int bh = blockIdx.x;
    int k  = blockIdx.y*256 + threadIdx.x;
    const float* base = g_S + (size_t)bh*Tt*Tt + k;
    float acc = 0.f;
    #pragma unroll 8
    for (int q=0;q<Tt;q++) acc += base[(size_t)q*Tt];
    g_w[bh*Tt + k] = acc;
}

// ---------------- o[b, h*E+e] = sum_k w[b,h,k] * V[b,k,h,e] ------------------
__global__ __launch_bounds__(128) void weighted_v()
{
    int b   = blockIdx.x;
    int col = blockIdx.y*128 + threadIdx.x;   // 0..4095, one h per CTA
    int h   = col >> 9;
    const float* wp = g_w + (size_t)(b*Hh + h)*Tt;
    const float* vp = g_V + (size_t)b*Tt*HE + col;
    float acc = 0.f;
    #pragma unroll 8
    for (int k=0;k<Tt;k++) acc += wp[k]*vp[(size_t)k*HE];
    g_o[b*HE + col] = acc;
}

// ---------------- u[b,j] = relu( o[b,:] @ Wu[:,j] + bu[j] ), 512 thr ---------
__global__ __launch_bounds__(512) void unify(const float* __restrict__ Wu,
                                             const float* __restrict__ bu)
{
    int b     = blockIdx.x;
    int j     = blockIdx.y*128 + (threadIdx.x & 127);
    int slice = threadIdx.x >> 7;       // 0..3, each sums 1024 i's
    const float* op = g_o + b*HE;
    float acc = 0.f;
    int i0 = slice*1024;
    #pragma unroll 8
    for (int i=i0; i<i0+1024; i++) acc += op[i]*Wu[(size_t)i*Ee + j];
    __shared__ float red[512];
    red[threadIdx.x] = acc;
    __syncthreads();
    if (threadIdx.x < 128) {
        float v = red[threadIdx.x] + red[threadIdx.x+128]
                + red[threadIdx.x+256] + red[threadIdx.x+384] + bu[j];
        g_u[b*Ee + j] = fmaxf(v, 0.f);
    }
}

// ---------------- block reduce helper (128 threads) --------------------------
__device__ __forceinline__ float blkSum128(float v, float* s4)
{
    #pragma unroll
    for (int o=16;o>0;o>>=1) v += __shfl_xor_sync(0xffffffffu, v, o);
    if ((threadIdx.x&31)==0) s4[threadIdx.x>>5] = v;
    __syncthreads();
    float r = s4[0]+s4[1]+s4[2]+s4[3];
    __syncthreads();
    return r;
}

// ---------------- y1 = LN( x + u[b] broadcast ; g1,b1 ) ----------------------
__global__ __launch_bounds__(128) void ln1(const float* __restrict__ x,
                                           const float* __restrict__ g,
                                           const float* __restrict__ be)
{
    __shared__ float s4[4];
    int row = blockIdx.x;
    int b   = row >> 10;
    int tid = threadIdx.x;
    float4 v = ((const float4*)(x   + (size_t)row*Ee))[tid];
    float4 u = ((const float4*)(g_u + (size_t)b  *Ee))[tid];
    v.x+=u.x; v.y+=u.y; v.z+=u.z; v.w+=u.w;

    float mu = blkSum128(v.x+v.y+v.z+v.w, s4) * (1.f/Ee);
    float d0=v.x-mu, d1=v.y-mu, d2=v.z-mu, d3=v.w-mu;
    float var = blkSum128(d0*d0+d1*d1+d2*d2+d3*d3, s4) * (1.f/Ee);
    float is = rsqrtf(var + 1e-5f);

    float4 gg = ((const float4*)g )[tid];
    float4 bb = ((const float4*)be)[tid];
    float4 o;
    o.x = d0*is*gg.x + bb.x; o.y = d1*is*gg.y + bb.y;
    o.z = d2*is*gg.z + bb.z; o.w = d3*is*gg.w + bb.w;
    ((float4*)(g_y1 + (size_t)row*Ee))[tid] = o;
}

// ---------------- out = LN( y1 + r ; g2,b2 ) ---------------------------------
__global__ __launch_bounds__(128) void ln2(const float* __restrict__ g,
                                           const float* __restrict__ be,
                                           float* __restrict__ out)
{
    __shared__ float s4[4];
    int row = blockIdx.x;
    int tid = threadIdx.x;
    float4 v = ((const float4*)(g_y1 + (size_t)row*Ee))[tid];
    float4 u = ((const float4*)(g_r  + (size_t)row*Ee))[tid];
    v.x+=u.x; v.y+=u.y; v.z+=u.z; v.w+=u.w;

    float mu = blkSum128(v.x+v.y+v.z+v.w, s4) * (1.f/Ee);
    float d0=v.x-mu, d1=v.y-mu, d2=v.z-mu, d3=v.w-mu;
    float var = blkSum128(d0*d0+d1*d1+d2*d2+d3*d3, s4) * (1.f/Ee);
    float is = rsqrtf(var + 1e-5f);

    float4 gg = ((const float4*)g )[tid];
    float4 bb = ((const float4*)be)[tid];
    float4 o;
    o.x = d0*is*gg.x + bb.x; o.y = d1*is*gg.y + bb.y;
    o.z = d2*is*gg.z + bb.z; o.w = d3*is*gg.w + bb.w;
    ((float4*)(out + (size_t)row*Ee))[tid] = o;
}

// =============================================================================
extern "C" void kernel_launch(void* const* d_in, const int* in_sizes, int n_in,
                              void* d_out, int out_size)
{
    const float* x  = (const float*)d_in[0];
    const float* Wq = (const float*)d_in[1];
    const float* bq = (const float*)d_in[2];
    const float* Wk = (const float*)d_in[3];
    const float* bk = (const float*)d_in[4];
    const float* Wv = (const float*)d_in[5];
    const float* bv = (const float*)d_in[6];
    const float* Wu = (const float*)d_in[7];
    const float* bu = (const float*)d_in[8];
    const float* g1 = (const float*)d_in[9];
    const float* b1 = (const float*)d_in[10];
    const float* Wh = (const float*)d_in[11];
    const float* bh = (const float*)d_in[12];
    const float* g2 = (const float*)d_in[13];
    const float* b2 = (const float*)d_in[14];
    float* out = (float*)d_out;

    float *Qd, *Kd, *Vd, *Y1d, *Rd;
    cudaGetSymbolAddress((void**)&Qd,  g_Q);
    cudaGetSymbolAddress((void**)&Kd,  g_K);
    cudaGetSymbolAddress((void**)&Vd,  g_V);
    cudaGetSymbolAddress((void**)&Y1d, g_y1);
    cudaGetSymbolAddress((void**)&Rd,  g_r);

    // 1) QKV projections (bias folded; 1/sqrt(E) scaling deferred to scores)
    dim3 gQKV(HE/128, BT/128);
    gemm_nn_bias<0><<<gQKV, 256>>>(x, Wq, bq, Qd, BT, HE, Ee);
    gemm_nn_bias<0><<<gQKV, 256>>>(x, Wk, bk, Kd, BT, HE, Ee);
    gemm_nn_bias<0><<<gQKV, 256>>>(x, Wv, bv, Vd, BT, HE, Ee);

    // 2) scores S = (Q K^T)/E per (b,h)
    gemm_nt_scores<<<dim3(Tt/128, Tt/128, Bq*Hh), 256>>>();

    // 3) softmax rows in place
    softmax_inplace<<<Bq*Hh*Tt, 128>>>();

    // 4) column sums over q
    attn_colsum<<<dim3(Bq*Hh, Tt/256), 256>>>();

    // 5) o = sum_k w * V
    weighted_v<<<dim3(Bq, HE/128), 128>>>();

    // 6) u = relu(o @ Wu + bu)
    unify<<<dim3(Bq, Ee/128), 512>>>(Wu, bu);

    // 7) y1 = LN(x + u)
    ln1<<<BT, 128>>>(x, g1, b1);

    // 8) r = relu(y1 @ Wh + bh)
    gemm_nn_bias<1><<<dim3(Ee/128, BT/128), 256>>>(Y1d, Wh, bh, Rd, BT, Ee, Ee);

    // 9) out = LN(y1 + r)
    ln2<<<BT, 128>>>(g2, b2, out);
}

// round 4
// speedup vs baseline: 1.7840x; 1.7840x over previous
#include <cuda_runtime.h>
#include <cuda_bf16.h>
#include <math.h>
#include <stdint.h>

// Problem constants
#define Bq 8
#define Tt 1024
#define Ee 512
#define Hh 8
#define BT (Bq*Tt)     // 8192
#define HE (Hh*Ee)     // 4096
#define KP 1536        // split K' = 3*512
#define NIT 24         // KP/64

// ---------------- scratch (static device globals; no allocation) -------------
__device__ __nv_bfloat16 g_xs [(size_t)BT*KP];        // x split [h|h|l]
__device__ __nv_bfloat16 g_Wqt[(size_t)HE*KP];        // Wq^T split [h|l|h]
__device__ __nv_bfloat16 g_Wkt[(size_t)HE*KP];
__device__ __nv_bfloat16 g_Wvt[(size_t)HE*KP];
__device__ __nv_bfloat16 g_Wht[(size_t)Ee*KP];
__device__ __nv_bfloat16 g_Qs [(size_t)BT*Hh*KP];     // Q split per head [h|h|l]
__device__ __nv_bfloat16 g_Ks [(size_t)BT*Hh*KP];     // K split per head [h|l|h]
__device__ float g_V [(size_t)BT*HE];
__device__ float g_S [(size_t)Bq*Hh*Tt*Tt];
__device__ float g_w [Bq*Hh*Tt];
__device__ float g_o [Bq*HE];
__device__ float g_u [Bq*Ee];
__device__ float g_y1[(size_t)BT*Ee];
__device__ __nv_bfloat16 g_y1s[(size_t)BT*KP];        // y1 split [h|h|l]
__device__ float g_r [(size_t)BT*Ee];

// ================= helpers ===================================================
__device__ __forceinline__ uint32_t smem_u32(const void* p) {
    uint32_t a;
    asm("{ .reg .u64 t; cvta.to.shared.u64 t, %1; cvt.u32.u64 %0, t; }" : "=r"(a) : "l"(p));
    return a;
}
#define CP_ASYNC16(dst, src) \
    asm volatile("cp.async.cg.shared.global [%0], [%1], 16;" :: "r"(dst), "l"(src))
#define CP_COMMIT() asm volatile("cp.async.commit_group;")
#define CP_WAIT1()  asm volatile("cp.async.wait_group 1;")
#define CP_WAIT0()  asm volatile("cp.async.wait_group 0;")
#define LDSM_X4(r0,r1,r2,r3,addr) \
    asm volatile("ldmatrix.sync.aligned.m8n8.x4.shared.b16 {%0,%1,%2,%3}, [%4];" \
        : "=r"(r0),"=r"(r1),"=r"(r2),"=r"(r3) : "r"(addr))

__device__ __forceinline__ void mma_bf16(float* d, const uint32_t* a,
                                         uint32_t b0, uint32_t b1) {
    asm volatile(
        "mma.sync.aligned.m16n8k16.row.col.f32.bf16.bf16.f32 "
        "{%0,%1,%2,%3}, {%4,%5,%6,%7}, {%8,%9}, {%0,%1,%2,%3};"
        : "+f"(d[0]), "+f"(d[1]), "+f"(d[2]), "+f"(d[3])
        : "r"(a[0]), "r"(a[1]), "r"(a[2]), "r"(a[3]), "r"(b0), "r"(b1));
}

// =============================================================================
// bf16 warp-MMA GEMM: C[128y,128x] (+z) = A'[128, K'=1536] . B'[128, K']^T
// MODE 0: C fp32 = acc*scale (+bias)          (V projection, scores)
// MODE 1: C fp32 = relu(acc + bias)           (Wh gemm)
// MODE 2: Q split -> OS pattern [h|h|l] per head-block
// MODE 3: K split -> OS pattern [h|l|h]
// =============================================================================
#define DYN_SMEM 65536
#define CS_LD 66

template<int MODE>
__global__ __launch_bounds__(256) void gemm_mma(
    const __nv_bfloat16* __restrict__ A, const __nv_bfloat16* __restrict__ B,
    float* __restrict__ C, __nv_bfloat16* __restrict__ OS,
    int lda, int ldb, int ldc,
    long long sAb, long long sAh, long long sBb, long long sBh, long long sCz,
    const float* __restrict__ bias, float scale)
{
    extern __shared__ char smem[];
    uint32_t sb = smem_u32(smem);
    const int tid = threadIdx.x, wid = tid >> 5, lid = tid & 31;
    const int z = blockIdx.z, zb = z >> 3, zh = z & 7;
    const int row0 = blockIdx.y * 128, col0 = blockIdx.x * 128;
    const int wm = wid & 1, wn = wid >> 1;   // 2 x 4 warp grid, warp tile 64x32

    const __nv_bfloat16* Ap = A + (size_t)zb*sAb + (size_t)zh*sAh + (size_t)row0*lda;
    const __nv_bfloat16* Bp = B + (size_t)zb*sBb + (size_t)zh*sBh + (size_t)col0*ldb;

    // gmem->smem mapping: thread t handles row t>>1, 4 x 16B units (t&1)*4+q
    const int lrow = tid >> 1, lcb = (tid & 1) * 4;
    uint32_t soff[4];
    #pragma unroll
    for (int q = 0; q < 4; q++) {
        uint32_t c = lcb + q;
        soff[q] = lrow*128 + (((c ^ (lrow & 7)) & 7) << 4);
    }
    const __nv_bfloat16* Asrc = Ap + (size_t)lrow*lda + lcb*8;
    const __nv_bfloat16* Bsrc = Bp + (size_t)lrow*ldb + lcb*8;

    float acc[4][4][4];
    #pragma unroll
    for (int i = 0; i < 4; i++)
        #pragma unroll
        for (int j = 0; j < 4; j++)
            #pragma unroll
            for (int r = 0; r < 4; r++) acc[i][j][r] = 0.f;

    // prologue: load tile 0 into buf 0
    {
        uint32_t aB = sb, bB = sb + 16384;
        #pragma unroll
        for (int q = 0; q < 4; q++) CP_ASYNC16(aB + soff[q], Asrc + q*8);
        #pragma unroll
        for (int q = 0; q < 4; q++) CP_ASYNC16(bB + soff[q], Bsrc + q*8);
        CP_COMMIT();
    }

    // precompute ldmatrix row components
    int arow[4], brow[2];
    #pragma unroll
    for (int mf = 0; mf < 4; mf++)
        arow[mf] = wm*64 + mf*16 + (lid & 7) + ((lid >> 3) & 1) * 8;
    #pragma unroll
    for (int ng = 0; ng < 2; ng++)
        brow[ng] = wn*32 + ng*16 + (lid & 7) + ((lid >> 3) & 1) * 8;
    const int ckl = (lid >> 4);   // 0 or 1

    for (int it = 0; it < NIT; it++) {
        int buf = it & 1;
        if (it + 1 < NIT) {
            int nb = (it + 1) & 1;
            uint32_t aB = sb + nb*32768, bB = sb + nb*32768 + 16384;
            const __nv_bfloat16* as = Asrc + (it + 1) * 64;
            const __nv_bfloat16* bs = Bsrc + (it + 1) * 64;
            #pragma unroll
            for (int q = 0; q < 4; q++) CP_ASYNC16(aB + soff[q], as + q*8);
            #pragma unroll
            for (int q = 0; q < 4; q++) CP_ASYNC16(bB + soff[q], bs + q*8);
            CP_COMMIT();
            CP_WAIT1();
        } else {
            CP_WAIT0();
        }
        __syncthreads();

        uint32_t aB = sb + buf*32768, bB = sb + buf*32768 + 16384;
        #pragma unroll
        for (int ks = 0; ks < 4; ks++) {
            int ck = ks*2 + ckl;
            uint32_t af[4][4], bf[2][4];
            #pragma unroll
            for (int mf = 0; mf < 4; mf++) {
                uint32_t ad = aB + arow[mf]*128 + (((ck ^ (arow[mf] & 7)) & 7) << 4);
                LDSM_X4(af[mf][0], af[mf][1], af[mf][2], af[mf][3], ad);
            }
            #pragma unroll
            for (int ng = 0; ng < 2; ng++) {
                uint32_t bd = bB + brow[ng]*128 + (((ck ^ (brow[ng] & 7)) & 7) << 4);
                LDSM_X4(bf[ng][0], bf[ng][1], bf[ng][2], bf[ng][3], bd);
            }
            #pragma unroll
            for (int mf = 0; mf < 4; mf++)
                #pragma unroll
                for (int ng = 0; ng < 2; ng++) {
                    mma_bf16(acc[mf][ng*2+0], af[mf], bf[ng][0], bf[ng][2]);
                    mma_bf16(acc[mf][ng*2+1], af[mf], bf[ng][1], bf[ng][3]);
                }
        }
        __syncthreads();
    }

    // -------- epilogue: two 64-col passes staged through smem ----------------
    float* Cs = (float*)smem;
    const int hblk = col0 >> 9;
    #pragma unroll
    for (int ch = 0; ch < 2; ch++) {
        __syncthreads();
        if ((wn >> 1) == ch) {
            #pragma unroll
            for (int mf = 0; mf < 4; mf++)
                #pragma unroll
                for (int nf = 0; nf < 4; nf++) {
                    int ccol = (wn & 1)*32 + nf*8 + 2*(lid & 3);
                    int crow = wm*64 + mf*16 + (lid >> 2);
                    Cs[crow*CS_LD + ccol]     = acc[mf][nf][0];
                    Cs[crow*CS_LD + ccol + 1] = acc[mf][nf][1];
                    Cs[(crow+8)*CS_LD + ccol]     = acc[mf][nf][2];
                    Cs[(crow+8)*CS_LD + ccol + 1] = acc[mf][nf][3];
                }
        }
        __syncthreads();

        int c = lid * 2;
        int gcol = col0 + ch*64 + c;
        for (int rr = wid; rr < 128; rr += 8) {
            int gr = row0 + rr;
            float v0 = Cs[rr*CS_LD + c], v1 = Cs[rr*CS_LD + c + 1];
            if (MODE == 0) {
                v0 *= scale; v1 *= scale;
                if (bias) {
                    float2 bb = *(const float2*)(bias + gcol);
                    v0 += bb.x; v1 += bb.y;
                }
                float2 o = {v0, v1};
                *(float2*)(C + (size_t)z*sCz + (size_t)gr*ldc + gcol) = o;
            } else if (MODE == 1) {
                float2 bb = *(const float2*)(bias + gcol);
                float2 o;
                o.x = fmaxf(v0 + bb.x, 0.f);
                o.y = fmaxf(v1 + bb.y, 0.f);
                *(float2*)(C + (size_t)gr*ldc + gcol) = o;
            } else {
                float2 bb = *(const float2*)(bias + gcol);
                v0 += bb.x; v1 += bb.y;
                __nv_bfloat16 h0 = __float2bfloat16(v0), h1 = __float2bfloat16(v1);
                __nv_bfloat16 l0 = __float2bfloat16(v0 - __bfloat162float(h0));
                __nv_bfloat16 l1 = __float2bfloat16(v1 - __bfloat162float(h1));
                __nv_bfloat162 hp = {h0, h1}, lp = {l0, l1};
                int e0 = (col0 & 511) + ch*64 + c;
                __nv_bfloat16* base = OS + (size_t)gr*(Hh*KP) + (size_t)hblk*KP + e0;
                if (MODE == 2) {  // [h|h|l]
                    *(__nv_bfloat162*)(base +    0) = hp;
                    *(__nv_bfloat162*)(base +  512) = hp;
                    *(__nv_bfloat162*)(base + 1024) = lp;
                } else {          // [h|l|h]
                    *(__nv_bfloat162*)(base +    0) = hp;
                    *(__nv_bfloat162*)(base +  512) = lp;
                    *(__nv_bfloat162*)(base + 1024) = hp;
                }
            }
        }
    }
}

// ---------------- split x: [BT,512] f32 -> [BT,1536] bf16 [h|h|l] ------------
__global__ __launch_bounds__(128) void splitx(const float* __restrict__ x,
                                              __nv_bfloat16* __restrict__ o)
{
    int r = blockIdx.x;
    int c = blockIdx.y*128 + threadIdx.x;
    float v = x[(size_t)r*Ee + c];
    __nv_bfloat16 h = __float2bfloat16(v);
    __nv_bfloat16 l = __float2bfloat16(v - __bfloat162float(h));
    __nv_bfloat16* b = o + (size_t)r*KP;
    b[c] = h; b[512 + c] = h; b[1024 + c] = l;
}

// ---------------- transpose + split W: [512,N] f32 -> [N,1536] bf16 [h|l|h] --
__global__ __launch_bounds__(256) void wsplit(const float* __restrict__ W,
                                              __nv_bfloat16* __restrict__ Wt, int N)
{
    __shared__ float t[32][33];
    int n0 = blockIdx.x*32, k0 = blockIdx.y*32;
    int tx = threadIdx.x & 31, ty = threadIdx.x >> 5;
    #pragma unroll
    for (int i = ty; i < 32; i += 8) t[i][tx] = W[(size_t)(k0+i)*N + n0+tx];
    __syncthreads();
    #pragma unroll
    for (int i = ty; i < 32; i += 8) {
        float v = t[tx][i];
        __nv_bfloat16 h = __float2bfloat16(v);
        __nv_bfloat16 l = __float2bfloat16(v - __bfloat162float(h));
        __nv_bfloat16* b = Wt + (size_t)(n0+i)*KP + k0;
        b[tx] = h; b[512 + tx] = l; b[1024 + tx] = h;
    }
}

// ---------------- softmax over each score row (in place) ---------------------
__global__ __launch_bounds__(128) void softmax_inplace()
{
    float* row = g_S + (size_t)blockIdx.x * Tt;
    int tid = threadIdx.x;
    float4 v0 = ((float4*)row)[tid];
    float4 v1 = ((float4*)row)[tid + 128];
    float m = fmaxf(fmaxf(fmaxf(v0.x,v0.y),fmaxf(v0.z,v0.w)),
                    fmaxf(fmaxf(v1.x,v1.y),fmaxf(v1.z,v1.w)));
    #pragma unroll
    for (int o = 16; o > 0; o >>= 1) m = fmaxf(m, __shfl_xor_sync(0xffffffffu, m, o));
    __shared__ float sm[4], ss[4];
    if ((tid&31)==0) sm[tid>>5] = m;
    __syncthreads();
    m = fmaxf(fmaxf(sm[0],sm[1]), fmaxf(sm[2],sm[3]));
    v0.x = expf(v0.x-m); v0.y = expf(v0.y-m); v0.z = expf(v0.z-m); v0.w = expf(v0.w-m);
    v1.x = expf(v1.x-m); v1.y = expf(v1.y-m); v1.z = expf(v1.z-m); v1.w = expf(v1.w-m);
    float s = v0.x+v0.y+v0.z+v0.w + v1.x+v1.y+v1.z+v1.w;
    #pragma unroll
    for (int o = 16; o > 0; o >>= 1) s += __shfl_xor_sync(0xffffffffu, s, o);
    if ((tid&31)==0) ss[tid>>5] = s;
    __syncthreads();
    s = ss[0]+ss[1]+ss[2]+ss[3];
    float inv = 1.f / s;
    v0.x*=inv; v0.y*=inv; v0.z*=inv; v0.w*=inv;
    v1.x*=inv; v1.y*=inv; v1.z*=inv; v1.w*=inv;
    ((float4*)row)[tid]       = v0;
    ((float4*)row)[tid + 128] = v1;
}

// ---------------- w[bh,k] = sum_q attn[bh,q,k] -------------------------------
__global__ __launch_bounds__(256) void attn_colsum()
{
    int bh = blockIdx.x;
    int k  = blockIdx.y*256 + threadIdx.x;
    const float* base = g_S + (size_t)bh*Tt*Tt + k;
    float acc = 0.f;
    #pragma unroll 8
    for (int q = 0; q < Tt; q++) acc += base[(size_t)q*Tt];
    g_w[bh*Tt + k] = acc;
}

// ---------------- o[b, h*E+e] = sum_k w[b,h,k] * V[b,k,h,e] ------------------
__global__ __launch_bounds__(128) void weighted_v()
{
    int b   = blockIdx.x;
    int col = blockIdx.y*128 + threadIdx.x;
    int h   = col >> 9;
    const float* wp = g_w + (size_t)(b*Hh + h)*Tt;
    const float* vp = g_V + (size_t)b*Tt*HE + col;
    float acc = 0.f;
    #pragma unroll 8
    for (int k = 0; k < Tt; k++) acc += wp[k]*vp[(size_t)k*HE];
    g_o[b*HE + col] = acc;
}

// ---------------- u[b,j] = relu( o[b,:] @ Wu[:,j] + bu[j] ) ------------------
__global__ __launch_bounds__(512) void unify(const float* __restrict__ Wu,
                                             const float* __restrict__ bu)
{
    int b     = blockIdx.x;
    int j     = blockIdx.y*128 + (threadIdx.x & 127);
    int slice = threadIdx.x >> 7;
    const float* op = g_o + b*HE;
    float acc = 0.f;
    int i0 = slice*1024;
    #pragma unroll 8
    for (int i = i0; i < i0+1024; i++) acc += op[i]*Wu[(size_t)i*Ee + j];
    __shared__ float red[512];
    red[threadIdx.x] = acc;
    __syncthreads();
    if (threadIdx.x < 128) {
        float v = red[threadIdx.x] + red[threadIdx.x+128]
                + red[threadIdx.x+256] + red[threadIdx.x+384] + bu[j];
        g_u[b*Ee + j] = fmaxf(v, 0.f);
    }
}

__device__ __forceinline__ float blkSum128(float v, float* s4)
{
    #pragma unroll
    for (int o = 16; o > 0; o >>= 1) v += __shfl_xor_sync(0xffffffffu, v, o);
    if ((threadIdx.x&31)==0) s4[threadIdx.x>>5] = v;
    __syncthreads();
    float r = s4[0]+s4[1]+s4[2]+s4[3];
    __syncthreads();
    return r;
}

// ---------------- y1 = LN(x + u[b]); also write y1 split [h|h|l] -------------
__global__ __launch_bounds__(128) void ln1(const float* __restrict__ x,
                                           const float* __restrict__ g,
                                           const float* __restrict__ be)
{
    __shared__ float s4[4];
    int row = blockIdx.x;
    int b   = row >> 10;
    int tid = threadIdx.x;
    float4 v = ((const float4*)(x   + (size_t)row*Ee))[tid];
    float4 u = ((const float4*)(g_u + (size_t)b  *Ee))[tid];
    v.x+=u.x; v.y+=u.y; v.z+=u.z; v.w+=u.w;
    float mu = blkSum128(v.x+v.y+v.z+v.w, s4) * (1.f/Ee);
    float d0=v.x-mu, d1=v.y-mu, d2=v.z-mu, d3=v.w-mu;
    float var = blkSum128(d0*d0+d1*d1+d2*d2+d3*d3, s4) * (1.f/Ee);
    float is = rsqrtf(var + 1e-5f);
    float4 gg = ((const float4*)g )[tid];
    float4 bb = ((const float4*)be)[tid];
    float4 o;
    o.x = d0*is*gg.x + bb.x; o.y = d1*is*gg.y + bb.y;
    o.z = d2*is*gg.z + bb.z; o.w = d3*is*gg.w + bb.w;
    ((float4*)(g_y1 + (size_t)row*Ee))[tid] = o;

    int c = tid*4;
    __nv_bfloat16* bse = g_y1s + (size_t)row*KP;
    __nv_bfloat16 h0=__float2bfloat16(o.x), h1=__float2bfloat16(o.y);
    __nv_bfloat16 h2=__float2bfloat16(o.z), h3=__float2bfloat16(o.w);
    __nv_bfloat16 l0=__float2bfloat16(o.x-__bfloat162float(h0));
    __nv_bfloat16 l1=__float2bfloat16(o.y-__bfloat162float(h1));
    __nv_bfloat16 l2=__float2bfloat16(o.z-__bfloat162float(h2));
    __nv_bfloat16 l3=__float2bfloat16(o.w-__bfloat162float(h3));
    __nv_bfloat162 hA={h0,h1}, hB={h2,h3}, lA={l0,l1}, lB={l2,l3};
    *(__nv_bfloat162*)(bse + c)          = hA; *(__nv_bfloat162*)(bse + c + 2)      = hB;
    *(__nv_bfloat162*)(bse + 512 + c)    = hA; *(__nv_bfloat162*)(bse + 512 + c+2)  = hB;
    *(__nv_bfloat162*)(bse + 1024 + c)   = lA; *(__nv_bfloat162*)(bse + 1024 + c+2) = lB;
}

// ---------------- out = LN(y1 + r) -------------------------------------------
__global__ __launch_bounds__(128) void ln2(const float* __restrict__ g,
                                           const float* __restrict__ be,
                                           float* __restrict__ out)
{
    __shared__ float s4[4];
    int row = blockIdx.x;
    int tid = threadIdx.x;
    float4 v = ((const float4*)(g_y1 + (size_t)row*Ee))[tid];
    float4 u = ((const float4*)(g_r  + (size_t)row*Ee))[tid];
    v.x+=u.x; v.y+=u.y; v.z+=u.z; v.w+=u.w;
    float mu = blkSum128(v.x+v.y+v.z+v.w, s4) * (1.f/Ee);
    float d0=v.x-mu, d1=v.y-mu, d2=v.z-mu, d3=v.w-mu;
    float var = blkSum128(d0*d0+d1*d1+d2*d2+d3*d3, s4) * (1.f/Ee);
    float is = rsqrtf(var + 1e-5f);
    float4 gg = ((const float4*)g )[tid];
    float4 bb = ((const float4*)be)[tid];
    float4 o;
    o.x = d0*is*gg.x + bb.x; o.y = d1*is*gg.y + bb.y;
    o.z = d2*is*gg.z + bb.z; o.w = d3*is*gg.w + bb.w;
    ((float4*)(out + (size_t)row*Ee))[tid] = o;
}

// =============================================================================
extern "C" void kernel_launch(void* const* d_in, const int* in_sizes, int n_in,
                              void* d_out, int out_size)
{
    const float* x  = (const float*)d_in[0];
    const float* Wq = (const float*)d_in[1];
    const float* bq = (const float*)d_in[2];
    const float* Wk = (const float*)d_in[3];
    const float* bk = (const float*)d_in[4];
    const float* Wv = (const float*)d_in[5];
    const float* bv = (const float*)d_in[6];
    const float* Wu = (const float*)d_in[7];
    const float* bu = (const float*)d_in[8];
    const float* g1 = (const float*)d_in[9];
    const float* b1 = (const float*)d_in[10];
    const float* Wh = (const float*)d_in[11];
    const float* bh = (const float*)d_in[12];
    const float* g2 = (const float*)d_in[13];
    const float* b2 = (const float*)d_in[14];
    float* out = (float*)d_out;

    cudaFuncSetAttribute(gemm_mma<0>, cudaFuncAttributeMaxDynamicSharedMemorySize, DYN_SMEM);
    cudaFuncSetAttribute(gemm_mma<1>, cudaFuncAttributeMaxDynamicSharedMemorySize, DYN_SMEM);
    cudaFuncSetAttribute(gemm_mma<2>, cudaFuncAttributeMaxDynamicSharedMemorySize, DYN_SMEM);
    cudaFuncSetAttribute(gemm_mma<3>, cudaFuncAttributeMaxDynamicSharedMemorySize, DYN_SMEM);

    __nv_bfloat16 *xs, *Wqt, *Wkt, *Wvt, *Wht, *Qs, *Ks, *Y1s;
    float *Vd, *Sd, *Rd;
    cudaGetSymbolAddress((void**)&xs,  g_xs);
    cudaGetSymbolAddress((void**)&Wqt, g_Wqt);
    cudaGetSymbolAddress((void**)&Wkt, g_Wkt);
    cudaGetSymbolAddress((void**)&Wvt, g_Wvt);
    cudaGetSymbolAddress((void**)&Wht, g_Wht);
    cudaGetSymbolAddress((void**)&Qs,  g_Qs);
    cudaGetSymbolAddress((void**)&Ks,  g_Ks);
    cudaGetSymbolAddress((void**)&Y1s, g_y1s);
    cudaGetSymbolAddress((void**)&Vd,  g_V);
    cudaGetSymbolAddress((void**)&Sd,  g_S);
    cudaGetSymbolAddress((void**)&Rd,  g_r);

    // 0) conversions / weight transposes
    splitx<<<dim3(BT, 4), 128>>>(x, xs);
    wsplit<<<dim3(HE/32, 16), 256>>>(Wq, Wqt, HE);
    wsplit<<<dim3(HE/32, 16), 256>>>(Wk, Wkt, HE);
    wsplit<<<dim3(HE/32, 16), 256>>>(Wv, Wvt, HE);
    wsplit<<<dim3(Ee/32, 16), 256>>>(Wh, Wht, Ee);

    // 1) QKV projections on tensor cores (mma.sync)
    dim3 gP(HE/128, BT/128, 1);
    gemm_mma<2><<<gP, 256, DYN_SMEM>>>(xs, Wqt, nullptr, Qs, KP, KP, 0, 0,0,0,0,0, bq, 1.f);
    gemm_mma<3><<<gP, 256, DYN_SMEM>>>(xs, Wkt, nullptr, Ks, KP, KP, 0, 0,0,0,0,0, bk, 1.f);
    gemm_mma<0><<<gP, 256, DYN_SMEM>>>(xs, Wvt, Vd, nullptr, KP, KP, HE, 0,0,0,0,0, bv, 1.f);

    // 2) scores: per (b,h) S = (Q.K^T)/E
    gemm_mma<0><<<dim3(Tt/128, Tt/128, Bq*Hh), 256, DYN_SMEM>>>(
        Qs, Ks, Sd, nullptr, Hh*KP, Hh*KP, Tt,
        (long long)Tt*Hh*KP, KP, (long long)Tt*Hh*KP, KP, (long long)Tt*Tt,
        nullptr, 1.f/(float)Ee);

    // 3) softmax rows in place
    softmax_inplace<<<Bq*Hh*Tt, 128>>>();

    // 4) column sums over q
    attn_colsum<<<dim3(Bq*Hh, Tt/256), 256>>>();

    // 5) o = sum_k w * V
    weighted_v<<<dim3(Bq, HE/128), 128>>>();

    // 6) u = relu(o @ Wu + bu)
    unify<<<dim3(Bq, Ee/128), 512>>>(Wu, bu);

    // 7) y1 = LN(x + u), plus split for next GEMM
    ln1<<<BT, 128>>>(x, g1, b1);

    // 8) r = relu(y1 @ Wh + bh) on tensor cores
    gemm_mma<1><<<dim3(Ee/128, BT/128, 1), 256, DYN_SMEM>>>(
        Y1s, Wht, Rd, nullptr, KP, KP, Ee, 0,0,0,0,0, bh, 1.f);

    // 9) out = LN(y1 + r)
    ln2<<<BT, 128>>>(g2, b2, out);
}